// round 12
// baseline (speedup 1.0000x reference)
#include <cuda_runtime.h>
#include <cuda_fp16.h>
#include <stdint.h>

#define N_NODES 10000
#define N_EDGES 160000
#define M_PAD   10112           // 79 * 128
#define SPLIT_M 5120            // 40 tiles chain A, 39 chain B

// ---------------- device scratch (no allocations allowed) ----------------
__device__ __half g_xh  [N_NODES * 256];  // x, fp16
__device__ __half g_aggx[M_PAD * 256];    // ÂX, fp16
__device__ __half g_h1  [M_PAD * 512];    // layer-1 out, fp16
__device__ __half g_xw2 [N_NODES * 256];  // h1 @ W2, fp16
__device__ __half g_w1t [512 * 256];      // W1^T, fp16
__device__ __half g_w2t [256 * 512];      // W2^T, fp16
__device__ unsigned g_mask1[160000];      // 5.12M dropout bits (layer 1)
__device__ unsigned g_mask2[80000];       // 2.56M dropout bits (layer 2)
__device__ float g_dinv[N_NODES];
__device__ int   g_cnt[N_NODES];          // zero at load; scan self-clears
__device__ int   g_off[N_NODES + 1];
__device__ int   g_cur[N_NODES];
__device__ int   g_csr[N_EDGES];

// ---------------- PTX helpers ----------------
__device__ __forceinline__ uint32_t smem_to_u32(const void* p) {
    uint32_t a;
    asm("{ .reg .u64 t; cvta.to.shared.u64 t, %1; cvt.u32.u64 %0, t; }" : "=r"(a) : "l"(p));
    return a;
}
__device__ __forceinline__ void cp_async16(uint32_t dst, const void* src) {
    asm volatile("cp.async.cg.shared.global [%0], [%1], 16;" :: "r"(dst), "l"(src));
}
#define CP_COMMIT()  asm volatile("cp.async.commit_group;" ::: "memory")
#define CP_WAIT(n)   asm volatile("cp.async.wait_group %0;" :: "n"(n) : "memory")

__device__ __forceinline__ void mma_f16(float* d, const uint32_t* a, const uint32_t* b) {
    asm volatile(
        "mma.sync.aligned.m16n8k16.row.col.f32.f16.f16.f32 "
        "{%0,%1,%2,%3},{%4,%5,%6,%7},{%8,%9},{%0,%1,%2,%3};"
        : "+f"(d[0]), "+f"(d[1]), "+f"(d[2]), "+f"(d[3])
        : "r"(a[0]), "r"(a[1]), "r"(a[2]), "r"(a[3]), "r"(b[0]), "r"(b[1]));
}

// ---------------- threefry2x32 (JAX-compatible, validated) ----------------
#define TF_ROUND(v0, v1, r) do { (v0) += (v1); (v1) = ((v1) << (r)) | ((v1) >> (32 - (r))); (v1) ^= (v0); } while (0)
__host__ __device__ inline void tf2x32(unsigned k0, unsigned k1,
                                       unsigned x0, unsigned x1,
                                       unsigned& o0, unsigned& o1) {
    unsigned ks0 = k0, ks1 = k1, ks2 = k0 ^ k1 ^ 0x1BD11BDAu;
    unsigned v0 = x0 + ks0, v1 = x1 + ks1;
    TF_ROUND(v0, v1, 13); TF_ROUND(v0, v1, 15); TF_ROUND(v0, v1, 26); TF_ROUND(v0, v1, 6);
    v0 += ks1; v1 += ks2 + 1u;
    TF_ROUND(v0, v1, 17); TF_ROUND(v0, v1, 29); TF_ROUND(v0, v1, 16); TF_ROUND(v0, v1, 24);
    v0 += ks2; v1 += ks0 + 2u;
    TF_ROUND(v0, v1, 13); TF_ROUND(v0, v1, 15); TF_ROUND(v0, v1, 26); TF_ROUND(v0, v1, 6);
    v0 += ks0; v1 += ks1 + 3u;
    TF_ROUND(v0, v1, 17); TF_ROUND(v0, v1, 29); TF_ROUND(v0, v1, 16); TF_ROUND(v0, v1, 24);
    v0 += ks1; v1 += ks2 + 4u;
    TF_ROUND(v0, v1, 13); TF_ROUND(v0, v1, 15); TF_ROUND(v0, v1, 26); TF_ROUND(v0, v1, 6);
    v0 += ks2; v1 += ks0 + 5u;
    o0 = v0; o1 = v1;
}

// ---------------- preprocessing --------------------------------------------
// ILP-5 count: 125 blocks x 256 threads x 5 edges = exactly 160000.
__global__ void count_kernel(const void* __restrict__ ei) {
    int e0 = (blockIdx.x * blockDim.x + threadIdx.x) * 5;
    const unsigned* u = (const unsigned*)ei;
    unsigned hior = 0;
#pragma unroll
    for (int j = 0; j < 5; j++) hior |= u[2u * (unsigned)(e0 + j) + 1u];
    bool is64 = !__any_sync(0xffffffffu, hior != 0u);
    int d[5];
    if (is64) {
        const long long* p = (const long long*)ei + N_EDGES + e0;
#pragma unroll
        for (int j = 0; j < 5; j++) d[j] = (int)p[j];
    } else {
        const int* p = (const int*)ei + N_EDGES + e0;
#pragma unroll
        for (int j = 0; j < 5; j++) d[j] = p[j];
    }
#pragma unroll
    for (int j = 0; j < 5; j++) atomicAdd(&g_cnt[d[j]], 1);
}

// one-pass scan: 1024 threads x 10 elements, 3 barriers total
__global__ void scan_kernel() {
    __shared__ int warp_pre[32];
    const int t = threadIdx.x;
    const int lane = t & 31, wid = t >> 5;
    const int base = t * 10;
    int v[10];
    int sum = 0;
#pragma unroll
    for (int j = 0; j < 10; j++) {
        int i = base + j;
        int c = (i < N_NODES) ? g_cnt[i] : 0;
        v[j] = c;
        sum += c;
        if (i < N_NODES) {
            g_dinv[i] = rsqrtf((float)(c + 1));
            g_cnt[i] = 0;                       // self-clear for graph replay
        }
    }
    int incl = sum;
#pragma unroll
    for (int o = 1; o < 32; o <<= 1) {
        int x = __shfl_up_sync(0xffffffffu, incl, o);
        if (lane >= o) incl += x;
    }
    if (lane == 31) warp_pre[wid] = incl;
    __syncthreads();
    if (wid == 0) {
        int ws = warp_pre[lane];
        int wincl = ws;
#pragma unroll
        for (int o = 1; o < 32; o <<= 1) {
            int x = __shfl_up_sync(0xffffffffu, wincl, o);
            if (lane >= o) wincl += x;
        }
        warp_pre[lane] = wincl - ws;
    }
    __syncthreads();
    int excl = incl - sum + warp_pre[wid];
#pragma unroll
    for (int j = 0; j < 10; j++) {
        int i = base + j;
        if (i < N_NODES) {
            g_off[i] = excl;
            g_cur[i] = excl;
        }
        excl += v[j];
    }
    if (base + 10 >= N_NODES && base < N_NODES) g_off[N_NODES] = excl;
}

// ILP-5 fill (same exact-coverage grid as count)
__global__ void fill_kernel(const void* __restrict__ ei) {
    int e0 = (blockIdx.x * blockDim.x + threadIdx.x) * 5;
    const unsigned* u = (const unsigned*)ei;
    unsigned hior = 0;
#pragma unroll
    for (int j = 0; j < 5; j++) hior |= u[2u * (unsigned)(e0 + j) + 1u];
    bool is64 = !__any_sync(0xffffffffu, hior != 0u);
    int s[5], d[5];
    if (is64) {
        const long long* ps = (const long long*)ei + e0;
        const long long* pd = (const long long*)ei + N_EDGES + e0;
#pragma unroll
        for (int j = 0; j < 5; j++) { s[j] = (int)ps[j]; d[j] = (int)pd[j]; }
    } else {
        const int* ps = (const int*)ei + e0;
        const int* pd = (const int*)ei + N_EDGES + e0;
#pragma unroll
        for (int j = 0; j < 5; j++) { s[j] = ps[j]; d[j] = pd[j]; }
    }
#pragma unroll
    for (int j = 0; j < 5; j++)
        g_csr[atomicAdd(&g_cur[d[j]], 1)] = s[j];
}

// x -> fp16 (vectorized)
__global__ void xh_kernel(const float* __restrict__ x) {
    int i = blockIdx.x * blockDim.x + threadIdx.x;   // float4 index
    float4 v = ((const float4*)x)[i];
    __half2 h0 = __floats2half2_rn(v.x, v.y);
    __half2 h1 = __floats2half2_rn(v.z, v.w);
    ((uint2*)g_xh)[i] = make_uint2(*(uint32_t*)&h0, *(uint32_t*)&h1);
}

// two transposes -> fp16
__global__ void transpose2_kernel(const float* __restrict__ W1,
                                  const float* __restrict__ W2) {
    __shared__ float tile[32][33];
    int z = blockIdx.z;
    const float* src = (z == 0) ? W1 : W2;
    __half* dst = (z == 0) ? g_w1t : g_w2t;
    int R = (z == 0) ? 256 : 512;
    int C = (z == 0) ? 512 : 256;
    if (blockIdx.x * 32 >= C || blockIdx.y * 32 >= R) return;
    int c0 = blockIdx.x * 32, r0 = blockIdx.y * 32;
#pragma unroll
    for (int i = 0; i < 32; i += 8) {
        int r = r0 + threadIdx.y + i, c = c0 + threadIdx.x;
        tile[threadIdx.y + i][threadIdx.x] = src[(size_t)r * C + c];
    }
    __syncthreads();
#pragma unroll
    for (int i = 0; i < 32; i += 8) {
        int c = c0 + threadIdx.y + i, r = r0 + threadIdx.x;
        dst[(size_t)c * R + r] = __float2half(tile[threadIdx.x][threadIdx.y + i]);
    }
}

// fused ILP-2 dropout bitmasks: blocks [0,10000) -> mask1 (5.12M elems),
// blocks [10000,15000) -> mask2 (2.56M elems). Each thread: 2 independent
// threefry evals (compiler interleaves the inlined chains -> ~2x issue eff).
__global__ void masks_kernel(unsigned* __restrict__ m1, unsigned* __restrict__ m2,
                             unsigned a0, unsigned a1, unsigned b0, unsigned b1) {
    unsigned blk = blockIdx.x;
    unsigned* mask;
    unsigned k0, k1, base;
    if (blk < 10000u) { mask = m1; k0 = a0; k1 = a1; base = blk * 512u; }
    else              { mask = m2; k0 = b0; k1 = b1; base = (blk - 10000u) * 512u; }
    unsigned i0 = base + threadIdx.x;
    unsigned i1 = i0 + 256u;
    unsigned y0, y1, z0, z1;
    tf2x32(k0, k1, 0u, i0, y0, y1);
    tf2x32(k0, k1, 0u, i1, z0, z1);
    unsigned ball0 = __ballot_sync(0xffffffffu, ((y0 ^ y1) >> 31) == 0u);
    unsigned ball1 = __ballot_sync(0xffffffffu, ((z0 ^ z1) >> 31) == 0u);
    if ((threadIdx.x & 31) == 0) {
        mask[i0 >> 5] = ball0;
        mask[i1 >> 5] = ball1;
    }
}

// ---------------- fp16 tensor-core GEMM -------------------------------------
#define SROW32 36
#define S_BUF32 (256 * SROW32)

template <int N_OUT, int K_TOT, int EPI>
__global__ void __launch_bounds__(256, 2)
hgemm_kernel(const __half* __restrict__ A, const __half* __restrict__ Bt,
             __half* __restrict__ C, const float* __restrict__ bias,
             const unsigned* __restrict__ mask, int M, int m0)
{
    extern __shared__ uint32_t sm32[];
    const int tid = threadIdx.x;
    const int wid = tid >> 5, lane = tid & 31;
    const int g = lane >> 2, tig = lane & 3;
    const int wm = wid >> 1, wn = wid & 1;
    const int bm = m0 + blockIdx.y * 128;
    const int bn = blockIdx.x * 128;
    constexpr int NBK = K_TOT / 64;

    const uint32_t sbase = smem_to_u32(sm32);

    float acc[2][8][4];
#pragma unroll
    for (int mi = 0; mi < 2; mi++)
#pragma unroll
        for (int ni = 0; ni < 8; ni++)
#pragma unroll
            for (int j = 0; j < 4; j++) acc[mi][ni][j] = 0.0f;

    auto load_tile = [&](int kc, int buf) {
#pragma unroll
        for (int r = 0; r < 4; r++) {
            int chunk = r * 256 + tid;
            int row = chunk >> 3;
            int f4  = chunk & 7;
            int gr = bm + row; if (gr >= M) gr = M - 1;
            uint32_t dA = sbase + (uint32_t)(buf * S_BUF32 + row * SROW32 + f4 * 4) * 4u;
            cp_async16(dA, A + (size_t)gr * K_TOT + kc * 64 + f4 * 8);
            int gn = bn + row;
            uint32_t dB = sbase + (uint32_t)(buf * S_BUF32 + (128 + row) * SROW32 + f4 * 4) * 4u;
            cp_async16(dB, Bt + (size_t)gn * K_TOT + kc * 64 + f4 * 8);
        }
    };

    load_tile(0, 0);
    CP_COMMIT();

    for (int kc = 0; kc < NBK; kc++) {
        int buf = kc & 1;
        if (kc + 1 < NBK) {
            load_tile(kc + 1, buf ^ 1);
            CP_COMMIT();
            CP_WAIT(1);
        } else {
            CP_WAIT(0);
        }
        __syncthreads();

        const uint32_t* As = sm32 + buf * S_BUF32;
        const uint32_t* Bs = As + 128 * SROW32;
        const int rm = wm * 32;
        const int cn = wn * 64;

#pragma unroll
        for (int s = 0; s < 4; s++) {
            int k0u = s * 8;
            uint32_t af[2][4];
#pragma unroll
            for (int mi = 0; mi < 2; mi++) {
                int r0 = rm + mi * 16 + g;
                af[mi][0] = As[r0 * SROW32 + k0u + tig];
                af[mi][1] = As[(r0 + 8) * SROW32 + k0u + tig];
                af[mi][2] = As[r0 * SROW32 + k0u + 4 + tig];
                af[mi][3] = As[(r0 + 8) * SROW32 + k0u + 4 + tig];
            }
#pragma unroll
            for (int ni = 0; ni < 8; ni++) {
                int n0 = cn + ni * 8 + g;
                uint32_t bf[2];
                bf[0] = Bs[n0 * SROW32 + k0u + tig];
                bf[1] = Bs[n0 * SROW32 + k0u + 4 + tig];
                mma_f16(acc[0][ni], af[0], bf);
                mma_f16(acc[1][ni], af[1], bf);
            }
        }
        __syncthreads();
    }

#pragma unroll
    for (int mi = 0; mi < 2; mi++) {
#pragma unroll
        for (int h = 0; h < 2; h++) {
            int m = bm + wm * 32 + mi * 16 + g + h * 8;
            if (m >= M) continue;
#pragma unroll
            for (int ni = 0; ni < 8; ni++) {
                int n0 = bn + wn * 64 + ni * 8 + tig * 2;
                float v0 = acc[mi][ni][h * 2 + 0];
                float v1 = acc[mi][ni][h * 2 + 1];
                if (EPI == 0) {
                    *(__half2*)(C + (size_t)m * N_OUT + n0) = __floats2half2_rn(v0, v1);
                } else {
                    float r0v = fmaxf(v0 + bias[n0], 0.0f);
                    float r1v = fmaxf(v1 + bias[n0 + 1], 0.0f);
                    unsigned idx = (unsigned)m * (unsigned)N_OUT + (unsigned)n0;
                    unsigned w = mask[idx >> 5];
                    r0v = ((w >> (idx & 31)) & 1u) ? r0v * 2.0f : 0.0f;
                    r1v = ((w >> ((idx + 1) & 31)) & 1u) ? r1v * 2.0f : 0.0f;
                    *(__half2*)(C + (size_t)m * N_OUT + n0) = __floats2half2_rn(r0v, r1v);
                }
            }
        }
    }
}

// ---------------- aggregations (half2 gathers) -------------------------------
__global__ void aggx_kernel(int base) {
    int n = base + blockIdx.x, c2 = threadIdx.x;
    float dn = g_dinv[n];
    float2 hv = __half22float2(((const __half2*)(g_xh + (size_t)n * 256))[c2]);
    float a0 = dn * hv.x, a1 = dn * hv.y;
    int k0 = g_off[n], k1 = g_off[n + 1];
    for (int k = k0; k < k1; k++) {
        int s = g_csr[k];
        float ds = g_dinv[s];
        float2 sv = __half22float2(((const __half2*)(g_xh + (size_t)s * 256))[c2]);
        a0 += ds * sv.x;
        a1 += ds * sv.y;
    }
    ((__half2*)(g_aggx + (size_t)n * 256))[c2] = __floats2half2_rn(a0 * dn, a1 * dn);
}

__global__ void agg2_kernel(const __half* __restrict__ xw,
                            const float* __restrict__ bias,
                            float* __restrict__ out,
                            const unsigned* __restrict__ mask) {
    int n = blockIdx.x, c2 = threadIdx.x;
    float dn = g_dinv[n];
    float2 hv = __half22float2(((const __half2*)(xw + (size_t)n * 256))[c2]);
    float a0 = dn * hv.x, a1 = dn * hv.y;
    int k0 = g_off[n], k1 = g_off[n + 1];
    for (int k = k0; k < k1; k++) {
        int s = g_csr[k];
        float ds = g_dinv[s];
        float2 sv = __half22float2(((const __half2*)(xw + (size_t)s * 256))[c2]);
        a0 += ds * sv.x;
        a1 += ds * sv.y;
    }
    int c = c2 * 2;
    float v0 = fmaxf(a0 * dn + bias[c], 0.0f);
    float v1 = fmaxf(a1 * dn + bias[c + 1], 0.0f);
    unsigned idx = (unsigned)(n * 256 + c);
    unsigned w = mask[idx >> 5];
    out[idx]     = ((w >> (idx & 31)) & 1u)       ? v0 * 2.0f : 0.0f;
    out[idx + 1] = ((w >> ((idx + 1) & 31)) & 1u) ? v1 * 2.0f : 0.0f;
}

// ---------------- launch -----------------------------------------------------
extern "C" void kernel_launch(void* const* d_in, const int* in_sizes, int n_in,
                              void* d_out, int out_size)
{
    const float* x  = (const float*)d_in[0];
    const void*  ei = d_in[1];
    const float* W1 = (const float*)d_in[2];
    const float* b1 = (const float*)d_in[3];
    const float* W2 = (const float*)d_in[4];
    const float* b2 = (const float*)d_in[5];
    float* out = (float*)d_out;

    __half *p_aggx, *p_h1, *p_xw2, *p_w1t, *p_w2t;
    unsigned *p_m1, *p_m2;
    cudaGetSymbolAddress((void**)&p_aggx, g_aggx);
    cudaGetSymbolAddress((void**)&p_h1,   g_h1);
    cudaGetSymbolAddress((void**)&p_xw2,  g_xw2);
    cudaGetSymbolAddress((void**)&p_w1t,  g_w1t);
    cudaGetSymbolAddress((void**)&p_w2t,  g_w2t);
    cudaGetSymbolAddress((void**)&p_m1,   g_mask1);
    cudaGetSymbolAddress((void**)&p_m2,   g_mask2);

    constexpr int SMEMB = 2 * S_BUF32 * 4;
    cudaFuncSetAttribute(hgemm_kernel<512, 256, 1>,
                         cudaFuncAttributeMaxDynamicSharedMemorySize, SMEMB);
    cudaFuncSetAttribute(hgemm_kernel<256, 512, 0>,
                         cudaFuncAttributeMaxDynamicSharedMemorySize, SMEMB);

    unsigned dk1_0, dk1_1, dk2_0, dk2_1;
    tf2x32(0u, 42u, 0u, 0u, dk1_0, dk1_1);
    tf2x32(0u, 42u, 0u, 1u, dk2_0, dk2_1);

    static cudaStream_t s1 = nullptr, s2 = nullptr;
    static cudaEvent_t ev_fork = nullptr, ev_xh = nullptr, ev_fill = nullptr,
                       ev_mk = nullptr, ev_b1 = nullptr;
    if (s1 == nullptr) {
        cudaStreamCreateWithFlags(&s1, cudaStreamNonBlocking);
        cudaStreamCreateWithFlags(&s2, cudaStreamNonBlocking);
        cudaEventCreateWithFlags(&ev_fork, cudaEventDisableTiming);
        cudaEventCreateWithFlags(&ev_xh,   cudaEventDisableTiming);
        cudaEventCreateWithFlags(&ev_fill, cudaEventDisableTiming);
        cudaEventCreateWithFlags(&ev_mk,   cudaEventDisableTiming);
        cudaEventCreateWithFlags(&ev_b1,   cudaEventDisableTiming);
    }

    cudaEventRecord(ev_fork, 0);

    // s2: transposes -> fused masks (both before the single gate, R9 ordering)
    cudaStreamWaitEvent(s2, ev_fork, 0);
    {
        dim3 blk(32, 8);
        transpose2_kernel<<<dim3(16, 16, 2), blk, 0, s2>>>(W1, W2);
    }
    masks_kernel<<<15000, 256, 0, s2>>>(p_m1, p_m2, dk1_0, dk1_1, dk2_0, dk2_1);
    cudaEventRecord(ev_mk, s2);

    // main stream: xh first (rebalances chains), then preproc, then aggxA
    xh_kernel<<<(N_NODES * 256 / 4) / 256, 256>>>(x);
    cudaEventRecord(ev_xh, 0);
    count_kernel<<<125, 256>>>(ei);
    scan_kernel<<<1, 1024>>>();
    fill_kernel<<<125, 256>>>(ei);
    cudaEventRecord(ev_fill, 0);
    aggx_kernel<<<SPLIT_M, 128>>>(0);

    // chain B on s1: aggxB overlaps aggxA / GEMM1A
    cudaStreamWaitEvent(s1, ev_fill, 0);
    cudaStreamWaitEvent(s1, ev_xh, 0);
    aggx_kernel<<<N_NODES - SPLIT_M, 128, 0, s1>>>(SPLIT_M);
    cudaStreamWaitEvent(s1, ev_mk, 0);
    hgemm_kernel<512, 256, 1><<<dim3(4, 39), 256, SMEMB, s1>>>(
        p_aggx, p_w1t, p_h1, b1, p_m1, N_NODES, SPLIT_M);
    cudaEventRecord(ev_b1, s1);

    // chain A on main
    cudaStreamWaitEvent(0, ev_mk, 0);
    hgemm_kernel<512, 256, 1><<<dim3(4, 40), 256, SMEMB>>>(
        p_aggx, p_w1t, p_h1, b1, p_m1, N_NODES, 0);

    // layer 2 (monolithic GEMM2, R9 style)
    cudaStreamWaitEvent(0, ev_b1, 0);
    hgemm_kernel<256, 512, 0><<<dim3(2, 79), 256, SMEMB>>>(
        p_h1, p_w2t, p_xw2, nullptr, nullptr, N_NODES, 0);
    agg2_kernel<<<N_NODES, 128>>>(p_xw2, b2, out, p_m2);
}

// round 13
// speedup vs baseline: 1.1567x; 1.1567x over previous
#include <cuda_runtime.h>
#include <cuda_fp16.h>
#include <stdint.h>

#define N_NODES 10000
#define N_EDGES 160000
#define M_PAD   10112           // 79 * 128
#define SPLIT_M 5120            // 40 tiles chain A, 39 chain B

// ---------------- device scratch (no allocations allowed) ----------------
__device__ __half g_xh  [N_NODES * 256];  // x, fp16
__device__ __half g_aggx[M_PAD * 256];    // ÂX, fp16
__device__ __half g_h1  [M_PAD * 512];    // layer-1 out, fp16
__device__ __half g_xw2 [N_NODES * 256];  // h1 @ W2, fp16
__device__ __half g_w1t [512 * 256];      // W1^T, fp16
__device__ __half g_w2t [256 * 512];      // W2^T, fp16
__device__ unsigned g_mask1[160000];      // 5.12M dropout bits (layer 1)
__device__ unsigned g_mask2[80000];       // 2.56M dropout bits (layer 2)
__device__ float g_dinv[N_NODES];
__device__ int   g_cnt[N_NODES];          // zero at load; scan self-clears
__device__ int   g_off[N_NODES + 1];
__device__ int   g_cur[N_NODES];
__device__ int   g_csr[N_EDGES];

// ---------------- PTX helpers ----------------
__device__ __forceinline__ uint32_t smem_to_u32(const void* p) {
    uint32_t a;
    asm("{ .reg .u64 t; cvta.to.shared.u64 t, %1; cvt.u32.u64 %0, t; }" : "=r"(a) : "l"(p));
    return a;
}
__device__ __forceinline__ void cp_async16(uint32_t dst, const void* src) {
    asm volatile("cp.async.cg.shared.global [%0], [%1], 16;" :: "r"(dst), "l"(src));
}
#define CP_COMMIT()  asm volatile("cp.async.commit_group;" ::: "memory")
#define CP_WAIT(n)   asm volatile("cp.async.wait_group %0;" :: "n"(n) : "memory")

__device__ __forceinline__ void mma_f16(float* d, const uint32_t* a, const uint32_t* b) {
    asm volatile(
        "mma.sync.aligned.m16n8k16.row.col.f32.f16.f16.f32 "
        "{%0,%1,%2,%3},{%4,%5,%6,%7},{%8,%9},{%0,%1,%2,%3};"
        : "+f"(d[0]), "+f"(d[1]), "+f"(d[2]), "+f"(d[3])
        : "r"(a[0]), "r"(a[1]), "r"(a[2]), "r"(a[3]), "r"(b[0]), "r"(b[1]));
}

// ---------------- threefry2x32 (JAX-compatible, validated) ----------------
#define TF_ROUND(v0, v1, r) do { (v0) += (v1); (v1) = ((v1) << (r)) | ((v1) >> (32 - (r))); (v1) ^= (v0); } while (0)
__host__ __device__ inline void tf2x32(unsigned k0, unsigned k1,
                                       unsigned x0, unsigned x1,
                                       unsigned& o0, unsigned& o1) {
    unsigned ks0 = k0, ks1 = k1, ks2 = k0 ^ k1 ^ 0x1BD11BDAu;
    unsigned v0 = x0 + ks0, v1 = x1 + ks1;
    TF_ROUND(v0, v1, 13); TF_ROUND(v0, v1, 15); TF_ROUND(v0, v1, 26); TF_ROUND(v0, v1, 6);
    v0 += ks1; v1 += ks2 + 1u;
    TF_ROUND(v0, v1, 17); TF_ROUND(v0, v1, 29); TF_ROUND(v0, v1, 16); TF_ROUND(v0, v1, 24);
    v0 += ks2; v1 += ks0 + 2u;
    TF_ROUND(v0, v1, 13); TF_ROUND(v0, v1, 15); TF_ROUND(v0, v1, 26); TF_ROUND(v0, v1, 6);
    v0 += ks0; v1 += ks1 + 3u;
    TF_ROUND(v0, v1, 17); TF_ROUND(v0, v1, 29); TF_ROUND(v0, v1, 16); TF_ROUND(v0, v1, 24);
    v0 += ks1; v1 += ks2 + 4u;
    TF_ROUND(v0, v1, 13); TF_ROUND(v0, v1, 15); TF_ROUND(v0, v1, 26); TF_ROUND(v0, v1, 6);
    v0 += ks2; v1 += ks0 + 5u;
    o0 = v0; o1 = v1;
}

// ---------------- preprocessing --------------------------------------------
// ILP-5 count: 125 blocks x 256 threads x 5 edges = exactly 160000.
__global__ void count_kernel(const void* __restrict__ ei) {
    int e0 = (blockIdx.x * blockDim.x + threadIdx.x) * 5;
    const unsigned* u = (const unsigned*)ei;
    unsigned hior = 0;
#pragma unroll
    for (int j = 0; j < 5; j++) hior |= u[2u * (unsigned)(e0 + j) + 1u];
    bool is64 = !__any_sync(0xffffffffu, hior != 0u);
    int d[5];
    if (is64) {
        const long long* p = (const long long*)ei + N_EDGES + e0;
#pragma unroll
        for (int j = 0; j < 5; j++) d[j] = (int)p[j];
    } else {
        const int* p = (const int*)ei + N_EDGES + e0;
#pragma unroll
        for (int j = 0; j < 5; j++) d[j] = p[j];
    }
#pragma unroll
    for (int j = 0; j < 5; j++) atomicAdd(&g_cnt[d[j]], 1);
}

// one-pass scan: 1024 threads x 10 elements, 3 barriers total
__global__ void scan_kernel() {
    __shared__ int warp_pre[32];
    const int t = threadIdx.x;
    const int lane = t & 31, wid = t >> 5;
    const int base = t * 10;
    int v[10];
    int sum = 0;
#pragma unroll
    for (int j = 0; j < 10; j++) {
        int i = base + j;
        int c = (i < N_NODES) ? g_cnt[i] : 0;
        v[j] = c;
        sum += c;
        if (i < N_NODES) {
            g_dinv[i] = rsqrtf((float)(c + 1));
            g_cnt[i] = 0;                       // self-clear for graph replay
        }
    }
    int incl = sum;
#pragma unroll
    for (int o = 1; o < 32; o <<= 1) {
        int x = __shfl_up_sync(0xffffffffu, incl, o);
        if (lane >= o) incl += x;
    }
    if (lane == 31) warp_pre[wid] = incl;
    __syncthreads();
    if (wid == 0) {
        int ws = warp_pre[lane];
        int wincl = ws;
#pragma unroll
        for (int o = 1; o < 32; o <<= 1) {
            int x = __shfl_up_sync(0xffffffffu, wincl, o);
            if (lane >= o) wincl += x;
        }
        warp_pre[lane] = wincl - ws;
    }
    __syncthreads();
    int excl = incl - sum + warp_pre[wid];
#pragma unroll
    for (int j = 0; j < 10; j++) {
        int i = base + j;
        if (i < N_NODES) {
            g_off[i] = excl;
            g_cur[i] = excl;
        }
        excl += v[j];
    }
    if (base + 10 >= N_NODES && base < N_NODES) g_off[N_NODES] = excl;
}

// ILP-5 fill (same exact-coverage grid as count)
__global__ void fill_kernel(const void* __restrict__ ei) {
    int e0 = (blockIdx.x * blockDim.x + threadIdx.x) * 5;
    const unsigned* u = (const unsigned*)ei;
    unsigned hior = 0;
#pragma unroll
    for (int j = 0; j < 5; j++) hior |= u[2u * (unsigned)(e0 + j) + 1u];
    bool is64 = !__any_sync(0xffffffffu, hior != 0u);
    int s[5], d[5];
    if (is64) {
        const long long* ps = (const long long*)ei + e0;
        const long long* pd = (const long long*)ei + N_EDGES + e0;
#pragma unroll
        for (int j = 0; j < 5; j++) { s[j] = (int)ps[j]; d[j] = (int)pd[j]; }
    } else {
        const int* ps = (const int*)ei + e0;
        const int* pd = (const int*)ei + N_EDGES + e0;
#pragma unroll
        for (int j = 0; j < 5; j++) { s[j] = ps[j]; d[j] = pd[j]; }
    }
#pragma unroll
    for (int j = 0; j < 5; j++)
        g_csr[atomicAdd(&g_cur[d[j]], 1)] = s[j];
}

// x -> fp16 (vectorized)
__global__ void xh_kernel(const float* __restrict__ x) {
    int i = blockIdx.x * blockDim.x + threadIdx.x;   // float4 index
    float4 v = ((const float4*)x)[i];
    __half2 h0 = __floats2half2_rn(v.x, v.y);
    __half2 h1 = __floats2half2_rn(v.z, v.w);
    ((uint2*)g_xh)[i] = make_uint2(*(uint32_t*)&h0, *(uint32_t*)&h1);
}

// two transposes -> fp16
__global__ void transpose2_kernel(const float* __restrict__ W1,
                                  const float* __restrict__ W2) {
    __shared__ float tile[32][33];
    int z = blockIdx.z;
    const float* src = (z == 0) ? W1 : W2;
    __half* dst = (z == 0) ? g_w1t : g_w2t;
    int R = (z == 0) ? 256 : 512;
    int C = (z == 0) ? 512 : 256;
    if (blockIdx.x * 32 >= C || blockIdx.y * 32 >= R) return;
    int c0 = blockIdx.x * 32, r0 = blockIdx.y * 32;
#pragma unroll
    for (int i = 0; i < 32; i += 8) {
        int r = r0 + threadIdx.y + i, c = c0 + threadIdx.x;
        tile[threadIdx.y + i][threadIdx.x] = src[(size_t)r * C + c];
    }
    __syncthreads();
#pragma unroll
    for (int i = 0; i < 32; i += 8) {
        int c = c0 + threadIdx.y + i, r = r0 + threadIdx.x;
        dst[(size_t)c * R + r] = __float2half(tile[threadIdx.x][threadIdx.y + i]);
    }
}

// ILP-2 dropout bitmask: each thread does 2 independent threefry evals
// (interleaved dep chains -> fills the 34% idle issue slots measured in R9).
// Grid covers n_elems/512 blocks. bit31 test == u < 0.5 (validated R10/R11).
__global__ void mask_kernel(unsigned* __restrict__ mask, unsigned k0, unsigned k1) {
    unsigned i0 = blockIdx.x * 512u + threadIdx.x;
    unsigned i1 = i0 + 256u;
    unsigned y0, y1, z0, z1;
    tf2x32(k0, k1, 0u, i0, y0, y1);
    tf2x32(k0, k1, 0u, i1, z0, z1);
    unsigned ball0 = __ballot_sync(0xffffffffu, ((y0 ^ y1) >> 31) == 0u);
    unsigned ball1 = __ballot_sync(0xffffffffu, ((z0 ^ z1) >> 31) == 0u);
    if ((threadIdx.x & 31) == 0) {
        mask[i0 >> 5] = ball0;
        mask[i1 >> 5] = ball1;
    }
}

// ---------------- fp16 tensor-core GEMM -------------------------------------
#define SROW32 36
#define S_BUF32 (256 * SROW32)

template <int N_OUT, int K_TOT, int EPI>
__global__ void __launch_bounds__(256, 2)
hgemm_kernel(const __half* __restrict__ A, const __half* __restrict__ Bt,
             __half* __restrict__ C, const float* __restrict__ bias,
             const unsigned* __restrict__ mask, int M, int m0)
{
    extern __shared__ uint32_t sm32[];
    const int tid = threadIdx.x;
    const int wid = tid >> 5, lane = tid & 31;
    const int g = lane >> 2, tig = lane & 3;
    const int wm = wid >> 1, wn = wid & 1;
    const int bm = m0 + blockIdx.y * 128;
    const int bn = blockIdx.x * 128;
    constexpr int NBK = K_TOT / 64;

    const uint32_t sbase = smem_to_u32(sm32);

    float acc[2][8][4];
#pragma unroll
    for (int mi = 0; mi < 2; mi++)
#pragma unroll
        for (int ni = 0; ni < 8; ni++)
#pragma unroll
            for (int j = 0; j < 4; j++) acc[mi][ni][j] = 0.0f;

    auto load_tile = [&](int kc, int buf) {
#pragma unroll
        for (int r = 0; r < 4; r++) {
            int chunk = r * 256 + tid;
            int row = chunk >> 3;
            int f4  = chunk & 7;
            int gr = bm + row; if (gr >= M) gr = M - 1;
            uint32_t dA = sbase + (uint32_t)(buf * S_BUF32 + row * SROW32 + f4 * 4) * 4u;
            cp_async16(dA, A + (size_t)gr * K_TOT + kc * 64 + f4 * 8);
            int gn = bn + row;
            uint32_t dB = sbase + (uint32_t)(buf * S_BUF32 + (128 + row) * SROW32 + f4 * 4) * 4u;
            cp_async16(dB, Bt + (size_t)gn * K_TOT + kc * 64 + f4 * 8);
        }
    };

    load_tile(0, 0);
    CP_COMMIT();

    for (int kc = 0; kc < NBK; kc++) {
        int buf = kc & 1;
        if (kc + 1 < NBK) {
            load_tile(kc + 1, buf ^ 1);
            CP_COMMIT();
            CP_WAIT(1);
        } else {
            CP_WAIT(0);
        }
        __syncthreads();

        const uint32_t* As = sm32 + buf * S_BUF32;
        const uint32_t* Bs = As + 128 * SROW32;
        const int rm = wm * 32;
        const int cn = wn * 64;

#pragma unroll
        for (int s = 0; s < 4; s++) {
            int k0u = s * 8;
            uint32_t af[2][4];
#pragma unroll
            for (int mi = 0; mi < 2; mi++) {
                int r0 = rm + mi * 16 + g;
                af[mi][0] = As[r0 * SROW32 + k0u + tig];
                af[mi][1] = As[(r0 + 8) * SROW32 + k0u + tig];
                af[mi][2] = As[r0 * SROW32 + k0u + 4 + tig];
                af[mi][3] = As[(r0 + 8) * SROW32 + k0u + 4 + tig];
            }
#pragma unroll
            for (int ni = 0; ni < 8; ni++) {
                int n0 = cn + ni * 8 + g;
                uint32_t bf[2];
                bf[0] = Bs[n0 * SROW32 + k0u + tig];
                bf[1] = Bs[n0 * SROW32 + k0u + 4 + tig];
                mma_f16(acc[0][ni], af[0], bf);
                mma_f16(acc[1][ni], af[1], bf);
            }
        }
        __syncthreads();
    }

#pragma unroll
    for (int mi = 0; mi < 2; mi++) {
#pragma unroll
        for (int h = 0; h < 2; h++) {
            int m = bm + wm * 32 + mi * 16 + g + h * 8;
            if (m >= M) continue;
#pragma unroll
            for (int ni = 0; ni < 8; ni++) {
                int n0 = bn + wn * 64 + ni * 8 + tig * 2;
                float v0 = acc[mi][ni][h * 2 + 0];
                float v1 = acc[mi][ni][h * 2 + 1];
                if (EPI == 0) {
                    *(__half2*)(C + (size_t)m * N_OUT + n0) = __floats2half2_rn(v0, v1);
                } else {
                    float r0v = fmaxf(v0 + bias[n0], 0.0f);
                    float r1v = fmaxf(v1 + bias[n0 + 1], 0.0f);
                    unsigned idx = (unsigned)m * (unsigned)N_OUT + (unsigned)n0;
                    unsigned w = mask[idx >> 5];
                    r0v = ((w >> (idx & 31)) & 1u) ? r0v * 2.0f : 0.0f;
                    r1v = ((w >> ((idx + 1) & 31)) & 1u) ? r1v * 2.0f : 0.0f;
                    *(__half2*)(C + (size_t)m * N_OUT + n0) = __floats2half2_rn(r0v, r1v);
                }
            }
        }
    }
}

// ---------------- aggregations (half2 gathers) -------------------------------
__global__ void aggx_kernel(int base) {
    int n = base + blockIdx.x, c2 = threadIdx.x;
    float dn = g_dinv[n];
    float2 hv = __half22float2(((const __half2*)(g_xh + (size_t)n * 256))[c2]);
    float a0 = dn * hv.x, a1 = dn * hv.y;
    int k0 = g_off[n], k1 = g_off[n + 1];
    for (int k = k0; k < k1; k++) {
        int s = g_csr[k];
        float ds = g_dinv[s];
        float2 sv = __half22float2(((const __half2*)(g_xh + (size_t)s * 256))[c2]);
        a0 += ds * sv.x;
        a1 += ds * sv.y;
    }
    ((__half2*)(g_aggx + (size_t)n * 256))[c2] = __floats2half2_rn(a0 * dn, a1 * dn);
}

__global__ void agg2_kernel(const __half* __restrict__ xw,
                            const float* __restrict__ bias,
                            float* __restrict__ out,
                            const unsigned* __restrict__ mask) {
    int n = blockIdx.x, c2 = threadIdx.x;
    float dn = g_dinv[n];
    float2 hv = __half22float2(((const __half2*)(xw + (size_t)n * 256))[c2]);
    float a0 = dn * hv.x, a1 = dn * hv.y;
    int k0 = g_off[n], k1 = g_off[n + 1];
    for (int k = k0; k < k1; k++) {
        int s = g_csr[k];
        float ds = g_dinv[s];
        float2 sv = __half22float2(((const __half2*)(xw + (size_t)s * 256))[c2]);
        a0 += ds * sv.x;
        a1 += ds * sv.y;
    }
    int c = c2 * 2;
    float v0 = fmaxf(a0 * dn + bias[c], 0.0f);
    float v1 = fmaxf(a1 * dn + bias[c + 1], 0.0f);
    unsigned idx = (unsigned)(n * 256 + c);
    unsigned w = mask[idx >> 5];
    out[idx]     = ((w >> (idx & 31)) & 1u)       ? v0 * 2.0f : 0.0f;
    out[idx + 1] = ((w >> ((idx + 1) & 31)) & 1u) ? v1 * 2.0f : 0.0f;
}

// ---------------- launch (exact R9 topology) ----------------------------------
extern "C" void kernel_launch(void* const* d_in, const int* in_sizes, int n_in,
                              void* d_out, int out_size)
{
    const float* x  = (const float*)d_in[0];
    const void*  ei = d_in[1];
    const float* W1 = (const float*)d_in[2];
    const float* b1 = (const float*)d_in[3];
    const float* W2 = (const float*)d_in[4];
    const float* b2 = (const float*)d_in[5];
    float* out = (float*)d_out;

    __half *p_aggx, *p_h1, *p_xw2, *p_w1t, *p_w2t;
    unsigned *p_m1, *p_m2;
    cudaGetSymbolAddress((void**)&p_aggx, g_aggx);
    cudaGetSymbolAddress((void**)&p_h1,   g_h1);
    cudaGetSymbolAddress((void**)&p_xw2,  g_xw2);
    cudaGetSymbolAddress((void**)&p_w1t,  g_w1t);
    cudaGetSymbolAddress((void**)&p_w2t,  g_w2t);
    cudaGetSymbolAddress((void**)&p_m1,   g_mask1);
    cudaGetSymbolAddress((void**)&p_m2,   g_mask2);

    constexpr int SMEMB = 2 * S_BUF32 * 4;
    cudaFuncSetAttribute(hgemm_kernel<512, 256, 1>,
                         cudaFuncAttributeMaxDynamicSharedMemorySize, SMEMB);
    cudaFuncSetAttribute(hgemm_kernel<256, 512, 0>,
                         cudaFuncAttributeMaxDynamicSharedMemorySize, SMEMB);

    unsigned dk1_0, dk1_1, dk2_0, dk2_1;
    tf2x32(0u, 42u, 0u, 0u, dk1_0, dk1_1);
    tf2x32(0u, 42u, 0u, 1u, dk2_0, dk2_1);

    static cudaStream_t s1 = nullptr, s2 = nullptr;
    static cudaEvent_t ev_fork = nullptr, ev_join = nullptr, ev_fill = nullptr,
                       ev_b1 = nullptr, ev_xh = nullptr;
    if (s1 == nullptr) {
        cudaStreamCreateWithFlags(&s1, cudaStreamNonBlocking);
        cudaStreamCreateWithFlags(&s2, cudaStreamNonBlocking);
        cudaEventCreateWithFlags(&ev_fork, cudaEventDisableTiming);
        cudaEventCreateWithFlags(&ev_join, cudaEventDisableTiming);
        cudaEventCreateWithFlags(&ev_fill, cudaEventDisableTiming);
        cudaEventCreateWithFlags(&ev_b1,   cudaEventDisableTiming);
        cudaEventCreateWithFlags(&ev_xh,   cudaEventDisableTiming);
    }

    cudaEventRecord(ev_fork, 0);

    // side stream (R9): xh -> transposes -> mask1 -> mask2 -> join
    cudaStreamWaitEvent(s2, ev_fork, 0);
    xh_kernel<<<(N_NODES * 256 / 4) / 256, 256, 0, s2>>>(x);
    cudaEventRecord(ev_xh, s2);
    {
        dim3 blk(32, 8);
        transpose2_kernel<<<dim3(16, 16, 2), blk, 0, s2>>>(W1, W2);
    }
    mask_kernel<<<10000, 256, 0, s2>>>(p_m1, dk1_0, dk1_1);   // 5.12M bits, ILP-2
    mask_kernel<<<5000, 256, 0, s2>>>(p_m2, dk2_0, dk2_1);    // 2.56M bits, ILP-2
    cudaEventRecord(ev_join, s2);

    // main stream: preproc (exact-coverage ILP-5 grids)
    count_kernel<<<125, 256>>>(ei);
    scan_kernel<<<1, 1024>>>();
    fill_kernel<<<125, 256>>>(ei);
    cudaEventRecord(ev_fill, 0);

    cudaStreamWaitEvent(0, ev_xh, 0);
    aggx_kernel<<<SPLIT_M, 128>>>(0);

    // chain B on s1 overlaps GEMM1A
    cudaStreamWaitEvent(s1, ev_fill, 0);
    cudaStreamWaitEvent(s1, ev_xh, 0);
    aggx_kernel<<<N_NODES - SPLIT_M, 128, 0, s1>>>(SPLIT_M);
    cudaStreamWaitEvent(s1, ev_join, 0);
    hgemm_kernel<512, 256, 1><<<dim3(4, 39), 256, SMEMB, s1>>>(
        p_aggx, p_w1t, p_h1, b1, p_m1, N_NODES, SPLIT_M);
    cudaEventRecord(ev_b1, s1);

    cudaStreamWaitEvent(0, ev_join, 0);
    hgemm_kernel<512, 256, 1><<<dim3(4, 40), 256, SMEMB>>>(
        p_aggx, p_w1t, p_h1, b1, p_m1, N_NODES, 0);

    // layer 2
    cudaStreamWaitEvent(0, ev_b1, 0);
    hgemm_kernel<256, 512, 0><<<dim3(2, 79), 256, SMEMB>>>(
        p_h1, p_w2t, p_xw2, nullptr, nullptr, N_NODES, 0);
    agg2_kernel<<<N_NODES, 128>>>(p_xw2, b2, out, p_m2);
}